// round 12
// baseline (speedup 1.0000x reference)
#include <cuda_runtime.h>
#include <math.h>

#define NBLK    128               // MUST be <= SM count (co-residency for barrier)
#define TPB     256
#define JN      128
#define MP      128
#define GRID    32                // 32x32 cells of size 0.25 over [-4,4]
#define NCELL   (GRID * GRID)
#define CCAP    128
#define CAP     4096              // per-patch segment capacity (max real ~1300)
#define SQCAP   1536              // smem queue per 256-point batch (expected ~655)
#define CHY     11                // process chunks per patch (11*128 = 1408 slots)
#define EPB     (TPB / 2)         // entries per pass (split-j: 2 threads/entry)

// scratch (zero-initialized at module load)
__device__ int      g_cellCnt[NCELL];
__device__ int      g_cellList[NCELL * CCAP];
__device__ int      g_cnt[MP];
__device__ int      g_idx[MP * CAP];
__device__ float2   g_std[MP * CAP];
__device__ unsigned g_arrive[NBLK];          // generation flags (monotonic)
__device__ volatile unsigned g_release;       // monotonic release word

__device__ __forceinline__ int cell_clamp(int i) { return min(GRID - 1, max(0, i)); }
__device__ __forceinline__ int cell_of(float v) {
    return cell_clamp((int)floorf((v + 4.0f) * 4.0f));
}

// ---------------------------------------------------------------------------
// software grid barrier. Safe because grid (128 blocks, 256 thr, ~22KB smem)
// is provably a single wave on a 148-SM chip. Generation numbers start from
// the pre-launch g_release value (read by every block BEFORE its first
// arrive; release only fires after all arrivals, so all blocks agree on the
// base) -> replay-safe with no reset.
// ---------------------------------------------------------------------------
__device__ __forceinline__ void grid_barrier(unsigned target)
{
    __threadfence();                  // every thread flushes its writes
    __syncthreads();
    if (blockIdx.x == 0) {
        if (threadIdx.x >= 1 && threadIdx.x < NBLK) {
            volatile unsigned* a = &((volatile unsigned*)g_arrive)[threadIdx.x];
            while (*a < target) __nanosleep(32);
        }
        __syncthreads();
        if (threadIdx.x == 0) g_release = target;
    } else {
        if (threadIdx.x == 0) {
            ((volatile unsigned*)g_arrive)[blockIdx.x] = target;
            while (g_release < target) __nanosleep(32);
        }
    }
    __syncthreads();
    __threadfence();
}

// ---------------------------------------------------------------------------
// fused kernel: bin -> barrier -> build -> barrier -> process
// ---------------------------------------------------------------------------
__global__ void __launch_bounds__(TPB)
rf_fused_kernel(const float2* __restrict__ p2, const float2* __restrict__ cs2,
                const float* __restrict__ W,  const float* __restrict__ b,
                const float* __restrict__ um, float* __restrict__ out, int N)
{
    __shared__ float2   scs[MP];
    __shared__ int      scnt[MP];
    __shared__ int      sbase[MP];
    __shared__ int      sqpos;
    __shared__ int      qmn[SQCAP];     // (m << 16) | n
    __shared__ float2   qs[SQCAP];
    __shared__ float4   sC[JN];
    __shared__ unsigned s_gen;

    const int tid  = threadIdx.x;
    const int lane = tid & 31;
    const int wid  = tid >> 5;

    if (tid == 0) s_gen = g_release;    // barrier generation base (stable pre-launch)
    for (int i = tid; i < MP; i += TPB) scs[i] = cs2[i];
    if (blockIdx.x == 0 && tid < MP) g_cnt[tid] = 0;   // per-call reset
    __syncthreads();
    const unsigned gen = s_gen;

    // ===== phase A: bin (warp-per-cell; 128 blocks x 8 warps = 1024 cells) ==
    {
        const int cell = blockIdx.x * (TPB / 32) + wid;
        const int ix = cell & (GRID - 1);
        const int iy = cell >> 5;
        const float x0 = -4.0f + 0.25f * ix, x1 = x0 + 0.25f;
        const float y0 = -4.0f + 0.25f * iy, y1 = y0 + 0.25f;
        const float R = 0.25001f;

        int* list = g_cellList + cell * CCAP;
        int cbase = 0;
        #pragma unroll
        for (int r = 0; r < MP / 32; r++) {
            const int m = r * 32 + lane;
            const float2 c = scs[m];
            const bool ovx = (c.x - R <= x1 || ix == GRID - 1) &&
                             (c.x + R >= x0 || ix == 0);
            const bool ovy = (c.y - R <= y1 || iy == GRID - 1) &&
                             (c.y + R >= y0 || iy == 0);
            const bool cand = ovx && ovy;
            const unsigned mask = __ballot_sync(0xFFFFFFFFu, cand);
            if (cand) list[cbase + __popc(mask & ((1u << lane) - 1))] = m;
            cbase += __popc(mask);
        }
        if (lane == 0) g_cellCnt[cell] = cbase;
    }

    grid_barrier(gen + 1);

    // ===== phase B: build (256 points per block per batch) ==================
    for (int nb = 0; nb < N; nb += NBLK * TPB) {
        for (int i = tid; i < MP; i += TPB) scnt[i] = 0;
        if (tid == 0) sqpos = 0;
        __syncthreads();

        const int n = nb + blockIdx.x * TPB + tid;
        float2 pv = make_float2(1e30f, 1e30f);
        int cell = 0, k = 0;
        if (n < N) {
            out[n] = 0.0f;                     // zero output (process is later)
            pv = p2[n];
            cell = (cell_of(pv.y) << 5) | cell_of(pv.x);
            k = g_cellCnt[cell];
        }
        const int kmax = __reduce_max_sync(0xFFFFFFFFu, k);

        for (int t = 0; t < kmax; t++) {
            const bool cand = (t < k);
            const int  m = cand ? g_cellList[cell * CCAP + t] : 0;
            const float2 c = scs[m];
            const float d0 = pv.x - c.x;
            const float d1 = pv.y - c.y;
            const bool hit = cand && (fabsf(d0) <= 0.25f) && (fabsf(d1) <= 0.25f);
            const unsigned mask = __ballot_sync(0xFFFFFFFFu, hit);
            if (mask) {
                const int cnt    = __popc(mask);
                const int leader = __ffs(mask) - 1;
                int wq = 0;
                if (lane == leader) wq = atomicAdd(&sqpos, cnt);
                wq = __shfl_sync(0xFFFFFFFFu, wq, leader);
                if (hit) {
                    const int pos = wq + __popc(mask & ((1u << lane) - 1));
                    if (pos < SQCAP) {
                        qmn[pos] = (m << 16) | (n & 0xFFFF);
                        qs[pos]  = make_float2(d0 * 4.0f, d1 * 4.0f);
                    }
                }
            }
        }
        __syncthreads();
        const int qtot = min(sqpos, SQCAP);

        for (int i = tid; i < qtot; i += TPB)
            atomicAdd(&scnt[qmn[i] >> 16], 1);
        __syncthreads();

        if (tid < MP) sbase[tid] = atomicAdd(&g_cnt[tid], scnt[tid]);
        __syncthreads();

        for (int i = tid; i < qtot; i += TPB) {
            const int key = qmn[i];
            const int m   = key >> 16;
            const int g   = atomicAdd(&sbase[m], 1);
            if (g < CAP) {
                const int at = m * CAP + g;
                g_idx[at] = nb + (key & 0xFFFF);
                g_std[at] = qs[i];
            }
        }
        __syncthreads();
    }

    grid_barrier(gen + 2);

    // ===== phase C: process (split-j; items span patches for balance) =======
    for (int item = blockIdx.x; item < MP * CHY; item += NBLK) {
        const int m = item / CHY;              // block's items span ~11 patches
        const int c = item - m * CHY;
        const int cnt = min(g_cnt[m], CAP);
        if (cnt <= c * EPB) continue;          // uniform per block

        __syncthreads();                       // previous item's sC readers done
        for (int j = tid; j < JN; j += TPB) {
            sC[j] = make_float4(W[m * (2 * JN) + j],
                                W[m * (2 * JN) + JN + j],
                                b[m * JN + j],
                                um[m * JN + j]);
        }
        __syncthreads();

        const int*    segN = g_idx + m * CAP;
        const float2* segS = g_std + m * CAP;
        const int jbase = (tid & 1) * (JN / 2);

        int i = c * EPB + (tid >> 1);
        while (__ballot_sync(0xFFFFFFFFu, i < cnt)) {
            const bool valid = (i < cnt);
            int    n = 0;
            float2 s = make_float2(0.0f, 0.0f);
            if (valid) { n = segN[i]; s = segS[i]; }

            float acc0 = 0.0f, acc1 = 0.0f;
            #pragma unroll 8
            for (int jj = 0; jj < JN / 2; jj += 2) {
                const float4 ca = sC[jbase + jj];
                const float4 cb = sC[jbase + jj + 1];
                float a0 = fmaf(s.x, ca.x, fmaf(s.y, ca.y, ca.z));
                float a1 = fmaf(s.x, cb.x, fmaf(s.y, cb.y, cb.z));
                float e0 = __expf(2.0f * a0);
                float e1 = __expf(2.0f * a1);
                float t0 = 1.0f - __fdividef(2.0f, e0 + 1.0f);
                float t1 = 1.0f - __fdividef(2.0f, e1 + 1.0f);
                acc0 = fmaf(t0, ca.w, acc0);
                acc1 = fmaf(t1, cb.w, acc1);
            }
            float acc = acc0 + acc1;
            acc += __shfl_xor_sync(0xFFFFFFFFu, acc, 1);
            if (valid && !(tid & 1)) atomicAdd(&out[n], acc);
            i += EPB * CHY;
        }
    }
}

// ---------------------------------------------------------------------------
// inputs (metadata order): p[N,2] f32, cs[128,2] f32, W[128,2,128] f32,
//                          b[128,128] f32, um[128,128] f32 ; out [N,1] f32
// ---------------------------------------------------------------------------
extern "C" void kernel_launch(void* const* d_in, const int* in_sizes, int n_in,
                              void* d_out, int out_size)
{
    const float* p  = (const float*)d_in[0];
    const float* cs = (const float*)d_in[1];
    const float* W  = (const float*)d_in[2];
    const float* b  = (const float*)d_in[3];
    const float* um = (const float*)d_in[4];
    float* out = (float*)d_out;

    const int N = in_sizes[0] / 2;   // 32768

    rf_fused_kernel<<<NBLK, TPB>>>((const float2*)p, (const float2*)cs,
                                   W, b, um, out, N);
}

// round 13
// speedup vs baseline: 1.5786x; 1.5786x over previous
#include <cuda_runtime.h>
#include <math.h>

#define NBLK    128               // binbuild grid; MUST be <= SM count (co-residency)
#define TPB     256
#define TPB_P   256
#define JN      128
#define MP      128
#define GRID    32                // 32x32 cells of size 0.25 over [-4,4]
#define NCELL   (GRID * GRID)
#define CCAP    128
#define CAP     4096              // per-patch segment capacity (max real ~1300)
#define SQCAP   1536              // smem queue per 256-point batch (expected ~655)
#define CHY     11                // process y-blocks per patch
#define EPB     (TPB_P / 2)       // entries per pass (split-j: 2 threads/entry)

// scratch (zero-initialized at module load)
__device__ int      g_cellCnt[NCELL];
__device__ int      g_cellList[NCELL * CCAP];
__device__ int      g_cnt[MP];
__device__ int      g_idx[MP * CAP];
__device__ float2   g_std[MP * CAP];
__device__ unsigned g_arrive[NBLK];          // generation flags (monotonic)
__device__ volatile unsigned g_release;       // monotonic release word

__device__ __forceinline__ int cell_clamp(int i) { return min(GRID - 1, max(0, i)); }
__device__ __forceinline__ int cell_of(float v) {
    return cell_clamp((int)floorf((v + 4.0f) * 4.0f));
}

// ---------------------------------------------------------------------------
// software grid barrier (proven in R12). Safe: 128 blocks x 256 thr, ~22KB
// smem -> single wave on this chip. Generations based on pre-launch
// g_release (read before any arrive; release fires only after all arrivals)
// -> graph-replay safe, no reset needed.
// ---------------------------------------------------------------------------
__device__ __forceinline__ void grid_barrier(unsigned target)
{
    __threadfence();
    __syncthreads();
    if (blockIdx.x == 0) {
        if (threadIdx.x >= 1 && threadIdx.x < NBLK) {
            volatile unsigned* a = &((volatile unsigned*)g_arrive)[threadIdx.x];
            while (*a < target) __nanosleep(32);
        }
        __syncthreads();
        if (threadIdx.x == 0) g_release = target;
    } else {
        if (threadIdx.x == 0) {
            ((volatile unsigned*)g_arrive)[blockIdx.x] = target;
            while (g_release < target) __nanosleep(32);
        }
    }
    __syncthreads();
    __threadfence();
}

// ---------------------------------------------------------------------------
// binbuild: phase A (warp-per-cell binning) -> grid barrier -> phase B
// (candidate scan + smem-queue compaction -> per-patch contiguous segments).
// Both phases are low-occupancy; fusing them saves a kernel boundary.
// |p-c| <= 0.25  <=>  |std| <= 1 exactly (x4 exact in fp32).
// ---------------------------------------------------------------------------
__global__ void __launch_bounds__(TPB)
rf_binbuild_kernel(const float2* __restrict__ p2, const float2* __restrict__ cs2,
                   float* __restrict__ out, int N)
{
    __shared__ float2   scs[MP];
    __shared__ int      scnt[MP];
    __shared__ int      sbase[MP];
    __shared__ int      sqpos;
    __shared__ int      qmn[SQCAP];     // (m << 16) | (n & 0xFFFF)
    __shared__ float2   qs[SQCAP];
    __shared__ unsigned s_gen;

    const int tid  = threadIdx.x;
    const int lane = tid & 31;
    const int wid  = tid >> 5;

    if (tid == 0) s_gen = g_release;    // stable pre-launch value
    for (int i = tid; i < MP; i += TPB) scs[i] = cs2[i];
    if (blockIdx.x == 0 && tid < MP) g_cnt[tid] = 0;   // per-call reset
    __syncthreads();
    const unsigned gen = s_gen;

    // ===== phase A: bin (warp-per-cell; 128 blocks x 8 warps = 1024 cells) ==
    {
        const int cell = blockIdx.x * (TPB / 32) + wid;
        const int ix = cell & (GRID - 1);
        const int iy = cell >> 5;
        const float x0 = -4.0f + 0.25f * ix, x1 = x0 + 0.25f;
        const float y0 = -4.0f + 0.25f * iy, y1 = y0 + 0.25f;
        const float R = 0.25001f;

        int* list = g_cellList + cell * CCAP;
        int cbase = 0;
        #pragma unroll
        for (int r = 0; r < MP / 32; r++) {
            const int m = r * 32 + lane;
            const float2 c = scs[m];
            const bool ovx = (c.x - R <= x1 || ix == GRID - 1) &&
                             (c.x + R >= x0 || ix == 0);
            const bool ovy = (c.y - R <= y1 || iy == GRID - 1) &&
                             (c.y + R >= y0 || iy == 0);
            const bool cand = ovx && ovy;
            const unsigned mask = __ballot_sync(0xFFFFFFFFu, cand);
            if (cand) list[cbase + __popc(mask & ((1u << lane) - 1))] = m;
            cbase += __popc(mask);
        }
        if (lane == 0) g_cellCnt[cell] = cbase;
    }

    grid_barrier(gen + 1);

    // ===== phase B: build (256 points per block per batch) ==================
    for (int nb = 0; nb < N; nb += NBLK * TPB) {
        for (int i = tid; i < MP; i += TPB) scnt[i] = 0;
        if (tid == 0) sqpos = 0;
        __syncthreads();

        const int n = nb + blockIdx.x * TPB + tid;
        float2 pv = make_float2(1e30f, 1e30f);
        int cell = 0, k = 0;
        if (n < N) {
            out[n] = 0.0f;                     // zero output (process runs later)
            pv = p2[n];
            cell = (cell_of(pv.y) << 5) | cell_of(pv.x);
            k = g_cellCnt[cell];
        }
        const int kmax = __reduce_max_sync(0xFFFFFFFFu, k);

        for (int t = 0; t < kmax; t++) {
            const bool cand = (t < k);
            const int  m = cand ? g_cellList[cell * CCAP + t] : 0;
            const float2 c = scs[m];
            const float d0 = pv.x - c.x;
            const float d1 = pv.y - c.y;
            const bool hit = cand && (fabsf(d0) <= 0.25f) && (fabsf(d1) <= 0.25f);
            const unsigned mask = __ballot_sync(0xFFFFFFFFu, hit);
            if (mask) {
                const int cnt    = __popc(mask);
                const int leader = __ffs(mask) - 1;
                int wq = 0;
                if (lane == leader) wq = atomicAdd(&sqpos, cnt);
                wq = __shfl_sync(0xFFFFFFFFu, wq, leader);
                if (hit) {
                    const int pos = wq + __popc(mask & ((1u << lane) - 1));
                    if (pos < SQCAP) {
                        qmn[pos] = (m << 16) | (n & 0xFFFF);
                        qs[pos]  = make_float2(d0 * 4.0f, d1 * 4.0f);
                    }
                }
            }
        }
        __syncthreads();
        const int qtot = min(sqpos, SQCAP);

        for (int i = tid; i < qtot; i += TPB)
            atomicAdd(&scnt[qmn[i] >> 16], 1);
        __syncthreads();

        if (tid < MP) sbase[tid] = atomicAdd(&g_cnt[tid], scnt[tid]);
        __syncthreads();

        for (int i = tid; i < qtot; i += TPB) {
            const int key = qmn[i];
            const int m   = key >> 16;
            const int g   = atomicAdd(&sbase[m], 1);
            if (g < CAP) {
                const int at = m * CAP + g;
                g_idx[at] = nb + (key & 0xFFFF);
                g_std[at] = qs[i];
            }
        }
        __syncthreads();
    }
}

// ---------------------------------------------------------------------------
// process (R11, measured-good): split-j — 2 threads per entry, each owns 64
// of the 128 j's, combined by one shfl_xor. High-occupancy grid (128 x 11
// blocks) hides the MUFU/FMA chain. tanh = 1 - 2/(exp(2x)+1), ~1e-7 rel.
// ---------------------------------------------------------------------------
__global__ void __launch_bounds__(TPB_P)
rf_process_kernel(const float* __restrict__ W, const float* __restrict__ b,
                  const float* __restrict__ um, float* __restrict__ out)
{
    const int m   = blockIdx.x;
    const int cnt = min(g_cnt[m], CAP);
    if (cnt <= blockIdx.y * EPB) return;          // uniform per block

    __shared__ float4 sC[JN];
    for (int j = threadIdx.x; j < JN; j += TPB_P) {
        sC[j] = make_float4(W[m * (2 * JN) + j],
                            W[m * (2 * JN) + JN + j],
                            b[m * JN + j],
                            um[m * JN + j]);
    }
    __syncthreads();

    const int*    segN = g_idx + m * CAP;
    const float2* segS = g_std + m * CAP;
    const int jbase = (threadIdx.x & 1) * (JN / 2);

    int i = blockIdx.y * EPB + (threadIdx.x >> 1);
    while (__ballot_sync(0xFFFFFFFFu, i < cnt)) {
        const bool valid = (i < cnt);
        int    n = 0;
        float2 s = make_float2(0.0f, 0.0f);
        if (valid) { n = segN[i]; s = segS[i]; }

        float acc0 = 0.0f, acc1 = 0.0f;
        #pragma unroll 8
        for (int jj = 0; jj < JN / 2; jj += 2) {
            const float4 ca = sC[jbase + jj];
            const float4 cb = sC[jbase + jj + 1];
            float a0 = fmaf(s.x, ca.x, fmaf(s.y, ca.y, ca.z));
            float a1 = fmaf(s.x, cb.x, fmaf(s.y, cb.y, cb.z));
            float e0 = __expf(2.0f * a0);
            float e1 = __expf(2.0f * a1);
            float t0 = 1.0f - __fdividef(2.0f, e0 + 1.0f);
            float t1 = 1.0f - __fdividef(2.0f, e1 + 1.0f);
            acc0 = fmaf(t0, ca.w, acc0);
            acc1 = fmaf(t1, cb.w, acc1);
        }
        float acc = acc0 + acc1;
        acc += __shfl_xor_sync(0xFFFFFFFFu, acc, 1);
        if (valid && !(threadIdx.x & 1)) atomicAdd(&out[n], acc);
        i += EPB * CHY;
    }
}

// ---------------------------------------------------------------------------
// inputs (metadata order): p[N,2] f32, cs[128,2] f32, W[128,2,128] f32,
//                          b[128,128] f32, um[128,128] f32 ; out [N,1] f32
// ---------------------------------------------------------------------------
extern "C" void kernel_launch(void* const* d_in, const int* in_sizes, int n_in,
                              void* d_out, int out_size)
{
    const float* p  = (const float*)d_in[0];
    const float* cs = (const float*)d_in[1];
    const float* W  = (const float*)d_in[2];
    const float* b  = (const float*)d_in[3];
    const float* um = (const float*)d_in[4];
    float* out = (float*)d_out;

    const int N = in_sizes[0] / 2;   // 32768

    rf_binbuild_kernel<<<NBLK, TPB>>>((const float2*)p, (const float2*)cs, out, N);

    dim3 pgrid(MP, CHY);
    rf_process_kernel<<<pgrid, TPB_P>>>(W, b, um, out);
}

// round 14
// speedup vs baseline: 1.5959x; 1.0110x over previous
#include <cuda_runtime.h>
#include <math.h>

#define TPB_B   256               // build block
#define TPB_P   128               // process block (finer grain)
#define JN      128
#define MP      128
#define GRID    32                // 32x32 cells of size 0.25 over [-4,4]
#define NCELL   (GRID * GRID)
#define CCAP    128
#define CAP     4096              // per-patch segment capacity (max real ~1300)
#define SQCAP   1536              // smem queue per build block (expected ~655)
#define CHY     22                // process y-blocks per patch (22*64 = 1408 slots)
#define EPB     (TPB_P / 2)       // 64 entries per pass (split-j: 2 threads/entry)

// scratch: static __device__ arrays (zero-initialized at module load)
__device__ int    g_cellCnt[NCELL];
__device__ int    g_cellList[NCELL * CCAP];
__device__ int    g_cnt[MP];
__device__ int    g_idx[MP * CAP];
__device__ float2 g_std[MP * CAP];

__device__ __forceinline__ int cell_clamp(int i) { return min(GRID - 1, max(0, i)); }
__device__ __forceinline__ int cell_of(float v) {
    return cell_clamp((int)floorf((v + 4.0f) * 4.0f));
}
__device__ __forceinline__ float frcp(float x) {
    float r; asm("rcp.approx.f32 %0, %1;" : "=f"(r) : "f"(x)); return r;
}
__device__ __forceinline__ float fex2(float x) {
    float r; asm("ex2.approx.f32 %0, %1;" : "=f"(r) : "f"(x)); return r;
}

// ---------------------------------------------------------------------------
// bin (R11, measured 4.4us): WARP-PER-CELL. 64 blocks x 512 = 1024 warps.
// Ballot + popc-prefix writes the compacted candidate list cooperatively.
// Margin 1e-5 kills fp edge false-negatives; edge cells extend outward for
// clamped points; exact |d|<=0.25 in build decides membership. Resets g_cnt.
// ---------------------------------------------------------------------------
__global__ void __launch_bounds__(512)
rf_bin_kernel(const float2* __restrict__ cs2)
{
    __shared__ float2 scs[MP];
    for (int i = threadIdx.x; i < MP; i += 512) scs[i] = cs2[i];
    __syncthreads();

    const int wid  = threadIdx.x >> 5;
    const int lane = threadIdx.x & 31;
    const int cell = blockIdx.x * 16 + wid;            // 0..1023
    if (blockIdx.x == 0 && threadIdx.x < MP) g_cnt[threadIdx.x] = 0;

    const int ix = cell & (GRID - 1);
    const int iy = cell >> 5;
    const float x0 = -4.0f + 0.25f * ix, x1 = x0 + 0.25f;
    const float y0 = -4.0f + 0.25f * iy, y1 = y0 + 0.25f;
    const float R = 0.25001f;

    int* list = g_cellList + cell * CCAP;
    int base = 0;
    #pragma unroll
    for (int r = 0; r < MP / 32; r++) {
        const int m = r * 32 + lane;
        const float2 c = scs[m];
        const bool ovx = (c.x - R <= x1 || ix == GRID - 1) &&
                         (c.x + R >= x0 || ix == 0);
        const bool ovy = (c.y - R <= y1 || iy == GRID - 1) &&
                         (c.y + R >= y0 || iy == 0);
        const bool cand = ovx && ovy;
        const unsigned mask = __ballot_sync(0xFFFFFFFFu, cand);
        if (cand) list[base + __popc(mask & ((1u << lane) - 1))] = m;
        base += __popc(mask);
    }
    if (lane == 0) g_cellCnt[cell] = base;
}

// ---------------------------------------------------------------------------
// build (R11, measured ~5.2us): 128 blocks x 256. Candidate scan via cell
// list, warp-aggregated smem queue, histogram -> one 128-wide global
// reservation wave -> cursor scatter into contiguous per-patch segments.
// ---------------------------------------------------------------------------
__global__ void __launch_bounds__(TPB_B)
rf_build_kernel(const float2* __restrict__ p2, const float2* __restrict__ cs2,
                float* __restrict__ out, int N)
{
    __shared__ float2 scs[MP];
    __shared__ int    scnt[MP];
    __shared__ int    sbase[MP];
    __shared__ int    sqpos;
    __shared__ int    qmn[SQCAP];     // (m << 16) | n
    __shared__ float2 qs[SQCAP];

    const int tid  = threadIdx.x;
    const int lane = tid & 31;

    for (int i = tid; i < MP; i += TPB_B) { scs[i] = cs2[i]; scnt[i] = 0; }
    if (tid == 0) sqpos = 0;
    __syncthreads();

    const int n = blockIdx.x * TPB_B + tid;
    float2 pv = make_float2(1e30f, 1e30f);
    int cell = 0, k = 0;
    if (n < N) {
        out[n] = 0.0f;                 // zero output (process runs later)
        pv = p2[n];
        cell = (cell_of(pv.y) << 5) | cell_of(pv.x);
        k = g_cellCnt[cell];
    }
    const int kmax = __reduce_max_sync(0xFFFFFFFFu, k);

    for (int t = 0; t < kmax; t++) {
        const bool cand = (t < k);
        const int  m = cand ? g_cellList[cell * CCAP + t] : 0;
        const float2 c = scs[m];
        const float d0 = pv.x - c.x;
        const float d1 = pv.y - c.y;
        const bool hit = cand && (fabsf(d0) <= 0.25f) && (fabsf(d1) <= 0.25f);
        const unsigned mask = __ballot_sync(0xFFFFFFFFu, hit);
        if (mask) {
            const int cnt    = __popc(mask);
            const int leader = __ffs(mask) - 1;
            int wq = 0;
            if (lane == leader) wq = atomicAdd(&sqpos, cnt);
            wq = __shfl_sync(0xFFFFFFFFu, wq, leader);
            if (hit) {
                const int pos = wq + __popc(mask & ((1u << lane) - 1));
                if (pos < SQCAP) {
                    qmn[pos] = (m << 16) | n;
                    qs[pos]  = make_float2(d0 * 4.0f, d1 * 4.0f);
                }
            }
        }
    }
    __syncthreads();
    const int qtot = min(sqpos, SQCAP);

    for (int i = tid; i < qtot; i += TPB_B)
        atomicAdd(&scnt[qmn[i] >> 16], 1);
    __syncthreads();

    if (tid < MP) sbase[tid] = atomicAdd(&g_cnt[tid], scnt[tid]);
    __syncthreads();

    for (int i = tid; i < qtot; i += TPB_B) {
        const int key = qmn[i];
        const int m   = key >> 16;
        const int g   = atomicAdd(&sbase[m], 1);
        if (g < CAP) {
            const int at = m * CAP + g;
            g_idx[at] = key & 0xFFFF;
            g_std[at] = qs[i];
        }
    }
}

// ---------------------------------------------------------------------------
// process: finer grain (128 threads, 64-entry quanta, 2816 blocks) + diet:
// coefficients prescaled by K = 2*log2(e) so tanh(a) = 1 - 2*rcp(ex2(a')+1)
// = fma(-2, rcp(ex2(a')+1), 1): 1 EX2 + 1 RCP + no extra muls per j.
// Saturates cleanly (ex2->inf => t->1; ex2->0 => t->-1). ~1e-7 rel.
// Split-j: 2 threads per entry (64 j's each), combined by one shfl_xor.
// ---------------------------------------------------------------------------
__global__ void __launch_bounds__(TPB_P)
rf_process_kernel(const float* __restrict__ W, const float* __restrict__ b,
                  const float* __restrict__ um, float* __restrict__ out)
{
    const int m   = blockIdx.x;
    const int cnt = min(g_cnt[m], CAP);
    if (cnt <= blockIdx.y * EPB) return;          // uniform per block

    __shared__ float4 sC[JN];
    const float K = 2.8853900817779268f;          // 2*log2(e)
    for (int j = threadIdx.x; j < JN; j += TPB_P) {
        sC[j] = make_float4(W[m * (2 * JN) + j] * K,
                            W[m * (2 * JN) + JN + j] * K,
                            b[m * JN + j] * K,
                            um[m * JN + j]);
    }
    __syncthreads();

    const int*    segN = g_idx + m * CAP;
    const float2* segS = g_std + m * CAP;
    const int jbase = (threadIdx.x & 1) * (JN / 2);

    int i = blockIdx.y * EPB + (threadIdx.x >> 1);
    while (__ballot_sync(0xFFFFFFFFu, i < cnt)) {
        const bool valid = (i < cnt);
        int    n = 0;
        float2 s = make_float2(0.0f, 0.0f);
        if (valid) { n = segN[i]; s = segS[i]; }

        float acc0 = 0.0f, acc1 = 0.0f;
        #pragma unroll 8
        for (int jj = 0; jj < JN / 2; jj += 2) {
            const float4 ca = sC[jbase + jj];
            const float4 cb = sC[jbase + jj + 1];
            float a0 = fmaf(s.x, ca.x, fmaf(s.y, ca.y, ca.z));
            float a1 = fmaf(s.x, cb.x, fmaf(s.y, cb.y, cb.z));
            float r0 = frcp(fex2(a0) + 1.0f);
            float r1 = frcp(fex2(a1) + 1.0f);
            float t0 = fmaf(-2.0f, r0, 1.0f);
            float t1 = fmaf(-2.0f, r1, 1.0f);
            acc0 = fmaf(t0, ca.w, acc0);
            acc1 = fmaf(t1, cb.w, acc1);
        }
        float acc = acc0 + acc1;
        acc += __shfl_xor_sync(0xFFFFFFFFu, acc, 1);  // combine j-halves
        if (valid && !(threadIdx.x & 1)) atomicAdd(&out[n], acc);
        i += EPB * CHY;
    }
}

// ---------------------------------------------------------------------------
// inputs (metadata order): p[N,2] f32, cs[128,2] f32, W[128,2,128] f32,
//                          b[128,128] f32, um[128,128] f32 ; out [N,1] f32
// ---------------------------------------------------------------------------
extern "C" void kernel_launch(void* const* d_in, const int* in_sizes, int n_in,
                              void* d_out, int out_size)
{
    const float* p  = (const float*)d_in[0];
    const float* cs = (const float*)d_in[1];
    const float* W  = (const float*)d_in[2];
    const float* b  = (const float*)d_in[3];
    const float* um = (const float*)d_in[4];
    float* out = (float*)d_out;

    const int N = in_sizes[0] / 2;   // 32768

    rf_bin_kernel<<<64, 512>>>((const float2*)cs);

    rf_build_kernel<<<(N + TPB_B - 1) / TPB_B, TPB_B>>>(
        (const float2*)p, (const float2*)cs, out, N);

    dim3 pgrid(MP, CHY);
    rf_process_kernel<<<pgrid, TPB_P>>>(W, b, um, out);
}